// round 3
// baseline (speedup 1.0000x reference)
#include <cuda_runtime.h>
#include <cstdint>

#define NN      100000
#define EE      800000
#define IN_DIM  384
#define HID     256
#define BN_EPS  1e-5f

// ---------------- device scratch (no malloc allowed) ----------------
__device__ float g_bufA[(size_t)NN * HID];   // 102.4 MB
__device__ float g_bufB[(size_t)NN * HID];   // 102.4 MB
__device__ float g_deg[NN];
__device__ float g_dinv[NN];
__device__ float g_invdeg[NN];
__device__ float g_stats[2 * HID];
__device__ float g_scale[HID];
__device__ float g_shift[HID];

// ---------------- small helpers ----------------
__global__ void k_zero(float* __restrict__ p, int n) {
    int i = blockIdx.x * blockDim.x + threadIdx.x;
    if (i < n) p[i] = 0.0f;
}

__global__ void k_count_deg(const int* __restrict__ dst, float* __restrict__ deg) {
    int e = blockIdx.x * blockDim.x + threadIdx.x;
    if (e < EE) atomicAdd(&deg[dst[e]], 1.0f);
}

__global__ void k_finalize_deg(const float* __restrict__ deg,
                               float* __restrict__ dinv,
                               float* __restrict__ invdeg) {
    int i = blockIdx.x * blockDim.x + threadIdx.x;
    if (i < NN) {
        float d = deg[i] + 1.0f;      // in-degree + self loop
        dinv[i]   = rsqrtf(d);
        invdeg[i] = 1.0f / d;
    }
}

// ---------------- SGEMM: C[M,256] = A[M,K] @ B[K,256] ----------------
// 128x128 block tile, BK=8, 256 threads, 8x8 register tile per thread.
__global__ __launch_bounds__(256)
void k_sgemm(const float* __restrict__ A, const float* __restrict__ B,
             float* __restrict__ C, int M, int K) {
    __shared__ float As[8][132];   // transposed A tile, 132 pitch -> conflict-free
    __shared__ float Bs[8][132];

    const int m0 = blockIdx.x * 128;
    const int n0 = blockIdx.y * 128;
    const int t  = threadIdx.x;
    const int tx = t & 15;         // 0..15
    const int ty = t >> 4;         // 0..15

    // global-load assignments
    const int aRow = t >> 1;            // 0..127
    const int aCol = (t & 1) * 4;       // 0 or 4
    const int bRow = t >> 5;            // 0..7
    const int bCol = (t & 31) * 4;      // 0..124

    const bool aValid = (m0 + aRow) < M;
    const float* Aptr = A + (size_t)(m0 + aRow) * K + aCol;
    const float* Bptr = B + (size_t)bRow * HID + n0 + bCol;

    float acc[8][8];
    #pragma unroll
    for (int i = 0; i < 8; i++)
        #pragma unroll
        for (int j = 0; j < 8; j++) acc[i][j] = 0.0f;

    for (int k0 = 0; k0 < K; k0 += 8) {
        float4 av = aValid ? *reinterpret_cast<const float4*>(Aptr)
                           : make_float4(0.f, 0.f, 0.f, 0.f);
        float4 bv = *reinterpret_cast<const float4*>(Bptr);
        Aptr += 8;
        Bptr += 8 * HID;

        __syncthreads();   // previous tile fully consumed
        As[aCol + 0][aRow] = av.x;
        As[aCol + 1][aRow] = av.y;
        As[aCol + 2][aRow] = av.z;
        As[aCol + 3][aRow] = av.w;
        *reinterpret_cast<float4*>(&Bs[bRow][bCol]) = bv;
        __syncthreads();

        #pragma unroll
        for (int k = 0; k < 8; k++) {
            float4 a0 = *reinterpret_cast<const float4*>(&As[k][ty * 4]);
            float4 a1 = *reinterpret_cast<const float4*>(&As[k][64 + ty * 4]);
            float4 b0 = *reinterpret_cast<const float4*>(&Bs[k][tx * 4]);
            float4 b1 = *reinterpret_cast<const float4*>(&Bs[k][64 + tx * 4]);
            float ar[8] = {a0.x, a0.y, a0.z, a0.w, a1.x, a1.y, a1.z, a1.w};
            float br[8] = {b0.x, b0.y, b0.z, b0.w, b1.x, b1.y, b1.z, b1.w};
            #pragma unroll
            for (int i = 0; i < 8; i++)
                #pragma unroll
                for (int j = 0; j < 8; j++)
                    acc[i][j] += ar[i] * br[j];
        }
    }

    #pragma unroll
    for (int i = 0; i < 8; i++) {
        int row = m0 + ty * 4 + (i & 3) + ((i >= 4) ? 64 : 0);
        if (row < M) {
            float4 v0 = make_float4(acc[i][0], acc[i][1], acc[i][2], acc[i][3]);
            float4 v1 = make_float4(acc[i][4], acc[i][5], acc[i][6], acc[i][7]);
            *reinterpret_cast<float4*>(C + (size_t)row * HID + n0 + tx * 4)      = v0;
            *reinterpret_cast<float4*>(C + (size_t)row * HID + n0 + 64 + tx * 4) = v1;
        }
    }
}

// ---------------- aggregation ----------------
// out[r,c] = h[r,c] * invdeg[r] + bias[c]     (initializes the scatter target)
__global__ void k_agg_init(float* __restrict__ out, const float* __restrict__ h,
                           const float* __restrict__ invdeg,
                           const float* __restrict__ bias) {
    int i = blockIdx.x * blockDim.x + threadIdx.x;     // float4 index
    if (i >= NN * (HID / 4)) return;
    int row = i >> 6;           // 64 float4 per row
    int c4  = i & 63;
    float id = invdeg[row];
    float4 hv = reinterpret_cast<const float4*>(h)[i];
    float4 bv = reinterpret_cast<const float4*>(bias)[c4];
    float4 o;
    o.x = hv.x * id + bv.x;
    o.y = hv.y * id + bv.y;
    o.z = hv.z * id + bv.z;
    o.w = hv.w * id + bv.w;
    reinterpret_cast<float4*>(out)[i] = o;
}

__device__ __forceinline__ void red_add4(float* p, float4 v) {
    asm volatile("red.global.add.v4.f32 [%0], {%1, %2, %3, %4};"
                 :: "l"(p), "f"(v.x), "f"(v.y), "f"(v.z), "f"(v.w) : "memory");
}

// one warp per edge: gather h[src] row, scale by coef, vector-red into agg[dst]
__global__ __launch_bounds__(256)
void k_scatter(float* __restrict__ agg, const float* __restrict__ h,
               const int* __restrict__ ei, const float* __restrict__ dinv) {
    int e = (blockIdx.x << 3) + (threadIdx.x >> 5);    // grid = EE/8 exactly
    int lane = threadIdx.x & 31;
    int src = __ldg(ei + e);
    int dst = __ldg(ei + EE + e);
    float coef = __ldg(dinv + src) * __ldg(dinv + dst);

    const float4* hp = reinterpret_cast<const float4*>(h + (size_t)src * HID);
    float4 v0 = __ldg(hp + lane * 2);
    float4 v1 = __ldg(hp + lane * 2 + 1);
    v0.x *= coef; v0.y *= coef; v0.z *= coef; v0.w *= coef;
    v1.x *= coef; v1.y *= coef; v1.z *= coef; v1.w *= coef;

    float* ap = agg + (size_t)dst * HID + lane * 8;
    red_add4(ap,     v0);
    red_add4(ap + 4, v1);
}

// ---------------- batchnorm ----------------
#define BN_ROWS 256
__global__ void k_bn_stats(const float* __restrict__ h, float* __restrict__ stats) {
    int c  = threadIdx.x;                 // 256 threads = one column each
    int r0 = blockIdx.x * BN_ROWS;
    int r1 = min(r0 + BN_ROWS, NN);
    float s = 0.f, s2 = 0.f;
    for (int r = r0; r < r1; r++) {
        float v = h[(size_t)r * HID + c];
        s += v;
        s2 += v * v;
    }
    atomicAdd(&stats[c], s);
    atomicAdd(&stats[HID + c], s2);
}

__global__ void k_bn_params(const float* __restrict__ stats,
                            const float* __restrict__ gamma,
                            const float* __restrict__ beta,
                            float* __restrict__ scale,
                            float* __restrict__ shift) {
    int c = threadIdx.x;
    if (c < HID) {
        const float inv_n = 1.0f / (float)NN;
        float mean = stats[c] * inv_n;
        float var  = fmaxf(stats[HID + c] * inv_n - mean * mean, 0.0f);
        float sc   = gamma[c] * rsqrtf(var + BN_EPS);
        scale[c] = sc;
        shift[c] = beta[c] - mean * sc;
    }
}

// out = relu(in * scale[c] + shift[c])   (in-place safe)
__global__ void k_bn_apply(float* __restrict__ out, const float* __restrict__ in,
                           const float* __restrict__ scale,
                           const float* __restrict__ shift) {
    int i = blockIdx.x * blockDim.x + threadIdx.x;     // float4 index
    if (i >= NN * (HID / 4)) return;
    int c4 = i & 63;
    float4 v  = reinterpret_cast<const float4*>(in)[i];
    float4 sc = reinterpret_cast<const float4*>(scale)[c4];
    float4 sh = reinterpret_cast<const float4*>(shift)[c4];
    float4 o;
    o.x = fmaxf(v.x * sc.x + sh.x, 0.0f);
    o.y = fmaxf(v.y * sc.y + sh.y, 0.0f);
    o.z = fmaxf(v.z * sc.z + sh.z, 0.0f);
    o.w = fmaxf(v.w * sc.w + sh.w, 0.0f);
    reinterpret_cast<float4*>(out)[i] = o;
}

// ---------------- launch ----------------
static float* sym(const void* devSym) {
    void* p = nullptr;
    cudaGetSymbolAddress(&p, devSym);
    return reinterpret_cast<float*>(p);
}

extern "C" void kernel_launch(void* const* d_in, const int* in_sizes, int n_in,
                              void* d_out, int out_size) {
    const float* x   = (const float*)d_in[0];
    const int*   ei  = (const int*)  d_in[1];
    const float* W1  = (const float*)d_in[2];
    const float* b1  = (const float*)d_in[3];
    const float* gm1 = (const float*)d_in[4];
    const float* be1 = (const float*)d_in[5];
    const float* W2  = (const float*)d_in[6];
    const float* b2  = (const float*)d_in[7];
    const float* gm2 = (const float*)d_in[8];
    const float* be2 = (const float*)d_in[9];
    float* out = (float*)d_out;

    float* bufA   = sym(g_bufA);
    float* bufB   = sym(g_bufB);
    float* deg    = sym(g_deg);
    float* dinv   = sym(g_dinv);
    float* invdeg = sym(g_invdeg);
    float* stats  = sym(g_stats);
    float* scale  = sym(g_scale);
    float* shift  = sym(g_shift);

    const int T = 256;
    const int elem4 = NN * (HID / 4);                  // 6.4M float4
    const dim3 gemmGrid((NN + 127) / 128, 2);
    const int ewGrid   = (elem4 + T - 1) / T;          // 25000
    const int scGrid   = EE / 8;                       // 100000
    const int statGrid = (NN + BN_ROWS - 1) / BN_ROWS; // 391

    // ---- degrees (shared by both layers) ----
    k_zero<<<(NN + T - 1) / T, T>>>(deg, NN);
    k_count_deg<<<(EE + T - 1) / T, T>>>(ei + EE, deg);
    k_finalize_deg<<<(NN + T - 1) / T, T>>>(deg, dinv, invdeg);

    // ---- layer 1 ----
    k_sgemm<<<gemmGrid, T>>>(x, W1, bufA, NN, IN_DIM);           // bufA = x @ W1
    k_agg_init<<<ewGrid, T>>>(bufB, bufA, invdeg, b1);           // bufB = self + bias
    k_scatter<<<scGrid, T>>>(bufB, bufA, ei, dinv);              // bufB += scatter msgs
    k_zero<<<2, T>>>(stats, 2 * HID);
    k_bn_stats<<<statGrid, T>>>(bufB, stats);
    k_bn_params<<<1, T>>>(stats, gm1, be1, scale, shift);
    k_bn_apply<<<ewGrid, T>>>(bufA, bufB, scale, shift);         // bufA = relu(bn(bufB))

    // ---- layer 2 ----
    k_sgemm<<<gemmGrid, T>>>(bufA, W2, bufB, NN, HID);           // bufB = h @ W2
    k_agg_init<<<ewGrid, T>>>(out, bufB, invdeg, b2);
    k_scatter<<<scGrid, T>>>(out, bufB, ei, dinv);
    k_zero<<<2, T>>>(stats, 2 * HID);
    k_bn_stats<<<statGrid, T>>>(out, stats);
    k_bn_params<<<1, T>>>(stats, gm2, be2, scale, shift);
    k_bn_apply<<<ewGrid, T>>>(out, out, scale, shift);           // in-place final
}

// round 8
// speedup vs baseline: 1.3925x; 1.3925x over previous
#include <cuda_runtime.h>
#include <cuda_bf16.h>
#include <cstdint>

#define NN      100000
#define EE      800000
#define IN_DIM  384
#define HID     256
#define BN_EPS  1e-5f

// ---------------- device scratch (no malloc allowed; 16B-aligned) ----------------
__device__ __align__(16) float g_bufA[(size_t)NN * HID];
__device__ __align__(16) float g_bufB[(size_t)NN * HID];
__device__ __align__(16) __nv_bfloat16 g_xhi[(size_t)NN * IN_DIM];
__device__ __align__(16) __nv_bfloat16 g_xlo[(size_t)NN * IN_DIM];
__device__ __align__(16) __nv_bfloat16 g_h1hi[(size_t)NN * HID];
__device__ __align__(16) __nv_bfloat16 g_h1lo[(size_t)NN * HID];
__device__ __align__(16) __nv_bfloat16 g_w1hi[IN_DIM * HID];   // [N=256, K=384] K-major
__device__ __align__(16) __nv_bfloat16 g_w1lo[IN_DIM * HID];
__device__ __align__(16) __nv_bfloat16 g_w2hi[HID * HID];      // [N=256, K=256] K-major
__device__ __align__(16) __nv_bfloat16 g_w2lo[HID * HID];
__device__ __align__(16) float g_deg[NN];
__device__ __align__(16) float g_dinv[NN];
__device__ __align__(16) float g_invdeg[NN];
__device__ __align__(16) float g_stats[2 * HID];
__device__ __align__(16) float g_scale[HID];
__device__ __align__(16) float g_shift[HID];

// ---------------- portable PTX helpers (sm_80-class: compile on base sm_103) ----
__device__ __forceinline__ uint32_t smem_u32(const void* p) {
    uint32_t a;
    asm("{ .reg .u64 t; cvta.to.shared.u64 t, %1; cvt.u32.u64 %0, t; }"
        : "=r"(a) : "l"(p));
    return a;
}

#define LDSM_X4(r, addr)                                                      \
    asm volatile("ldmatrix.sync.aligned.m8n8.x4.shared.b16 {%0,%1,%2,%3}, [%4];" \
                 : "=r"((r)[0]), "=r"((r)[1]), "=r"((r)[2]), "=r"((r)[3])     \
                 : "r"(addr))

#define MMA16816(d, a, b0, b1)                                                \
    asm volatile("mma.sync.aligned.m16n8k16.row.col.f32.bf16.bf16.f32 "       \
                 "{%0,%1,%2,%3}, {%4,%5,%6,%7}, {%8,%9}, {%0,%1,%2,%3};"      \
                 : "+f"((d)[0]), "+f"((d)[1]), "+f"((d)[2]), "+f"((d)[3])     \
                 : "r"((a)[0]), "r"((a)[1]), "r"((a)[2]), "r"((a)[3]),        \
                   "r"(b0), "r"(b1))

// ---------------- mma.sync split-bf16 GEMM ----------------
// C[M,256] = (Ahi+Alo)[M,K] @ (Bhi+Blo)^T,  B*[256,K] K-major.
// CTA tile 128x128, BK=32, 8 warps (warp tile 32x64), cp.async double buffer.
// Split precision: C ≈ Ahi·Bhi + Alo·Bhi + Ahi·Blo  (Alo·Blo ~2^-18, dropped).
#define BKC     32
#define PITCHB  80                      // 64B data + 16B pad: conflict-free ldmatrix
#define TILE_B  (128 * PITCHB)          // 10240 B per matrix tile
#define STAGE_B (4 * TILE_B)            // Ahi,Alo,Bhi,Blo = 40960 B
#define GEMM_SMEM (2 * STAGE_B)         // 81920 B double-buffered

__device__ __forceinline__ void load_stage(
    uint32_t sb, const __nv_bfloat16* Ahi, const __nv_bfloat16* Alo,
    const __nv_bfloat16* Bhi, const __nv_bfloat16* Blo,
    int m0, int n0, int kbase, int M, int K, int tid)
{
    #pragma unroll
    for (int q = 0; q < 8; q++) {
        int t   = q * 256 + tid;            // 0..2047
        int mat = t >> 9;                   // 0:Ahi 1:Alo 2:Bhi 3:Blo (uniform per q-pair)
        int r   = (t & 511) >> 2;           // row 0..127
        int c   = t & 3;                    // 16B chunk 0..3
        uint32_t dst = sb + mat * TILE_B + r * PITCHB + c * 16;
        const __nv_bfloat16* base =
            (mat == 0) ? Ahi : (mat == 1) ? Alo : (mat == 2) ? Bhi : Blo;
        int row   = (mat < 2) ? (m0 + r) : (n0 + r);
        int valid = 16;
        if (mat < 2 && row >= M) { row = M - 1; valid = 0; }   // ZFILL predication
        const void* src = base + (size_t)row * K + kbase + c * 8;
        asm volatile("cp.async.cg.shared.global [%0], [%1], 16, %2;"
                     :: "r"(dst), "l"(src), "r"(valid));
    }
    asm volatile("cp.async.commit_group;" ::: "memory");
}

__global__ __launch_bounds__(256)
void k_mma_gemm(const __nv_bfloat16* __restrict__ Ahi,
                const __nv_bfloat16* __restrict__ Alo,
                const __nv_bfloat16* __restrict__ Bhi,
                const __nv_bfloat16* __restrict__ Blo,
                float* __restrict__ C, int M, int K)
{
    extern __shared__ __align__(16) char sm[];
    const int tid  = threadIdx.x;
    const int lane = tid & 31;
    const int wid  = tid >> 5;
    const int m0   = blockIdx.x * 128;
    const int n0   = blockIdx.y * 128;
    const int wm   = (wid >> 1) << 5;       // warp m offset (0,32,64,96)
    const int wn   = (wid & 1) << 6;        // warp n offset (0,64)
    const uint32_t sbase = smem_u32(sm);

    float acc[2][8][4];
    #pragma unroll
    for (int i = 0; i < 2; i++)
        #pragma unroll
        for (int j = 0; j < 8; j++)
            #pragma unroll
            for (int k = 0; k < 4; k++) acc[i][j][k] = 0.0f;

    // ldmatrix per-lane address components
    const int arow      = lane & 15;
    const uint32_t acoff = (uint32_t)((lane >> 4) << 4);
    const int brow      = (lane & 7) + ((lane >> 4) << 3);
    const uint32_t bcoff = (uint32_t)(((lane >> 3) & 1) << 4);

    const int nst = K / BKC;
    load_stage(sbase, Ahi, Alo, Bhi, Blo, m0, n0, 0, M, K, tid);

    for (int kc = 0; kc < nst; kc++) {
        if (kc + 1 < nst) {
            load_stage(sbase + ((kc + 1) & 1) * STAGE_B, Ahi, Alo, Bhi, Blo,
                       m0, n0, (kc + 1) * BKC, M, K, tid);
            asm volatile("cp.async.wait_group 1;" ::: "memory");
        } else {
            asm volatile("cp.async.wait_group 0;" ::: "memory");
        }
        __syncthreads();

        const uint32_t sb = sbase + (kc & 1) * STAGE_B;
        #pragma unroll
        for (int ks = 0; ks < 2; ks++) {            // two k16 steps per BK=32
            const uint32_t kb2 = (uint32_t)(ks * 32);   // byte offset of k16 step
            uint32_t ah[2][4], al[2][4];
            #pragma unroll
            for (int i = 0; i < 2; i++) {
                uint32_t ad = sb + (uint32_t)((wm + i * 16 + arow) * PITCHB) + kb2 + acoff;
                LDSM_X4(ah[i], ad);
                LDSM_X4(al[i], ad + TILE_B);
            }
            #pragma unroll
            for (int j = 0; j < 4; j++) {           // each x4 covers two n8 tiles
                uint32_t bd = sb + 2 * TILE_B
                            + (uint32_t)((wn + j * 16 + brow) * PITCHB) + kb2 + bcoff;
                uint32_t bh[4], bl[4];
                LDSM_X4(bh, bd);
                LDSM_X4(bl, bd + TILE_B);
                #pragma unroll
                for (int i = 0; i < 2; i++) {
                    MMA16816(acc[i][2 * j],     ah[i], bh[0], bh[1]);
                    MMA16816(acc[i][2 * j],     al[i], bh[0], bh[1]);
                    MMA16816(acc[i][2 * j],     ah[i], bl[0], bl[1]);
                    MMA16816(acc[i][2 * j + 1], ah[i], bh[2], bh[3]);
                    MMA16816(acc[i][2 * j + 1], al[i], bh[2], bh[3]);
                    MMA16816(acc[i][2 * j + 1], ah[i], bl[2], bl[3]);
                }
            }
        }
        __syncthreads();    // protect buffer (kc&1) before it is refilled
    }

    // ---- epilogue: m16n8 accumulator mapping -> C ----
    #pragma unroll
    for (int i = 0; i < 2; i++) {
        int r0 = m0 + wm + i * 16 + (lane >> 2);
        #pragma unroll
        for (int j = 0; j < 8; j++) {
            int n = n0 + wn + j * 8 + ((lane & 3) << 1);
            if (r0 < M)
                *reinterpret_cast<float2*>(C + (size_t)r0 * HID + n) =
                    make_float2(acc[i][j][0], acc[i][j][1]);
            if (r0 + 8 < M)
                *reinterpret_cast<float2*>(C + (size_t)(r0 + 8) * HID + n) =
                    make_float2(acc[i][j][2], acc[i][j][3]);
        }
    }
}

// ---------------- split conversions ----------------
__global__ void k_split(const float* __restrict__ in,
                        __nv_bfloat16* __restrict__ hi,
                        __nv_bfloat16* __restrict__ lo, int n4) {
    int i = blockIdx.x * blockDim.x + threadIdx.x;
    if (i >= n4) return;
    float4 v = reinterpret_cast<const float4*>(in)[i];
    __nv_bfloat16 h0 = __float2bfloat16_rn(v.x);
    __nv_bfloat16 h1 = __float2bfloat16_rn(v.y);
    __nv_bfloat16 h2 = __float2bfloat16_rn(v.z);
    __nv_bfloat16 h3 = __float2bfloat16_rn(v.w);
    __nv_bfloat162* hp = reinterpret_cast<__nv_bfloat162*>(hi + (size_t)i * 4);
    __nv_bfloat162* lp = reinterpret_cast<__nv_bfloat162*>(lo + (size_t)i * 4);
    hp[0] = __nv_bfloat162(h0, h1);
    hp[1] = __nv_bfloat162(h2, h3);
    lp[0] = __nv_bfloat162(__float2bfloat16_rn(v.x - __bfloat162float(h0)),
                           __float2bfloat16_rn(v.y - __bfloat162float(h1)));
    lp[1] = __nv_bfloat162(__float2bfloat16_rn(v.z - __bfloat162float(h2)),
                           __float2bfloat16_rn(v.w - __bfloat162float(h3)));
}

// W [K,N] row-major -> transposed split [N,K]
__global__ void k_splitWT(const float* __restrict__ W,
                          __nv_bfloat16* __restrict__ hi,
                          __nv_bfloat16* __restrict__ lo, int K) {
    int i = blockIdx.x * blockDim.x + threadIdx.x;
    if (i >= K * HID) return;
    int k = i / HID, n = i % HID;
    float v = W[i];
    __nv_bfloat16 h = __float2bfloat16_rn(v);
    hi[(size_t)n * K + k] = h;
    lo[(size_t)n * K + k] = __float2bfloat16_rn(v - __bfloat162float(h));
}

// ---------------- small helpers ----------------
__global__ void k_zero(float* __restrict__ p, int n) {
    int i = blockIdx.x * blockDim.x + threadIdx.x;
    if (i < n) p[i] = 0.0f;
}

__global__ void k_count_deg(const int* __restrict__ dst, float* __restrict__ deg) {
    int e = blockIdx.x * blockDim.x + threadIdx.x;
    if (e < EE) atomicAdd(&deg[dst[e]], 1.0f);
}

__global__ void k_finalize_deg(const float* __restrict__ deg,
                               float* __restrict__ dinv,
                               float* __restrict__ invdeg) {
    int i = blockIdx.x * blockDim.x + threadIdx.x;
    if (i < NN) {
        float d = deg[i] + 1.0f;
        dinv[i]   = rsqrtf(d);
        invdeg[i] = 1.0f / d;
    }
}

// ---------------- aggregation ----------------
__global__ void k_agg_init(float* __restrict__ out, const float* __restrict__ h,
                           const float* __restrict__ invdeg,
                           const float* __restrict__ bias) {
    int i = blockIdx.x * blockDim.x + threadIdx.x;
    if (i >= NN * (HID / 4)) return;
    int row = i >> 6;
    int c4  = i & 63;
    float id = invdeg[row];
    float4 hv = reinterpret_cast<const float4*>(h)[i];
    float4 bv = reinterpret_cast<const float4*>(bias)[c4];
    float4 o;
    o.x = hv.x * id + bv.x;
    o.y = hv.y * id + bv.y;
    o.z = hv.z * id + bv.z;
    o.w = hv.w * id + bv.w;
    reinterpret_cast<float4*>(out)[i] = o;
}

__device__ __forceinline__ void red_add4(float* p, float4 v) {
    asm volatile("red.global.add.v4.f32 [%0], {%1, %2, %3, %4};"
                 :: "l"(p), "f"(v.x), "f"(v.y), "f"(v.z), "f"(v.w) : "memory");
}

__global__ __launch_bounds__(256)
void k_scatter(float* __restrict__ agg, const float* __restrict__ h,
               const int* __restrict__ ei, const float* __restrict__ dinv) {
    int e = (blockIdx.x << 3) + (threadIdx.x >> 5);
    int lane = threadIdx.x & 31;
    int src = __ldg(ei + e);
    int dst = __ldg(ei + EE + e);
    float coef = __ldg(dinv + src) * __ldg(dinv + dst);

    const float4* hp = reinterpret_cast<const float4*>(h + (size_t)src * HID);
    float4 v0 = __ldg(hp + lane * 2);
    float4 v1 = __ldg(hp + lane * 2 + 1);
    v0.x *= coef; v0.y *= coef; v0.z *= coef; v0.w *= coef;
    v1.x *= coef; v1.y *= coef; v1.z *= coef; v1.w *= coef;

    float* ap = agg + (size_t)dst * HID + lane * 8;
    red_add4(ap,     v0);
    red_add4(ap + 4, v1);
}

// ---------------- batchnorm ----------------
#define BN_ROWS 256
__global__ void k_bn_stats(const float* __restrict__ h, float* __restrict__ stats) {
    int c  = threadIdx.x;
    int r0 = blockIdx.x * BN_ROWS;
    int r1 = min(r0 + BN_ROWS, NN);
    float s = 0.f, s2 = 0.f;
    for (int r = r0; r < r1; r++) {
        float v = h[(size_t)r * HID + c];
        s += v;
        s2 += v * v;
    }
    atomicAdd(&stats[c], s);
    atomicAdd(&stats[HID + c], s2);
}

__global__ void k_bn_params(const float* __restrict__ stats,
                            const float* __restrict__ gamma,
                            const float* __restrict__ beta,
                            float* __restrict__ scale,
                            float* __restrict__ shift) {
    int c = threadIdx.x;
    if (c < HID) {
        const float inv_n = 1.0f / (float)NN;
        float mean = stats[c] * inv_n;
        float var  = fmaxf(stats[HID + c] * inv_n - mean * mean, 0.0f);
        float sc   = gamma[c] * rsqrtf(var + BN_EPS);
        scale[c] = sc;
        shift[c] = beta[c] - mean * sc;
    }
}

__global__ void k_bn_apply(float* __restrict__ out, const float* __restrict__ in,
                           const float* __restrict__ scale,
                           const float* __restrict__ shift) {
    int i = blockIdx.x * blockDim.x + threadIdx.x;
    if (i >= NN * (HID / 4)) return;
    int c4 = i & 63;
    float4 v  = reinterpret_cast<const float4*>(in)[i];
    float4 sc = reinterpret_cast<const float4*>(scale)[c4];
    float4 sh = reinterpret_cast<const float4*>(shift)[c4];
    float4 o;
    o.x = fmaxf(v.x * sc.x + sh.x, 0.0f);
    o.y = fmaxf(v.y * sc.y + sh.y, 0.0f);
    o.z = fmaxf(v.z * sc.z + sh.z, 0.0f);
    o.w = fmaxf(v.w * sc.w + sh.w, 0.0f);
    reinterpret_cast<float4*>(out)[i] = o;
}

// relu(bn(in)) -> split bf16 hi/lo (feeds layer-2 MMA directly)
__global__ void k_bn_apply_split(__nv_bfloat16* __restrict__ hi,
                                 __nv_bfloat16* __restrict__ lo,
                                 const float* __restrict__ in,
                                 const float* __restrict__ scale,
                                 const float* __restrict__ shift) {
    int i = blockIdx.x * blockDim.x + threadIdx.x;
    if (i >= NN * (HID / 4)) return;
    int c4 = i & 63;
    float4 v  = reinterpret_cast<const float4*>(in)[i];
    float4 sc = reinterpret_cast<const float4*>(scale)[c4];
    float4 sh = reinterpret_cast<const float4*>(shift)[c4];
    float o0 = fmaxf(v.x * sc.x + sh.x, 0.0f);
    float o1 = fmaxf(v.y * sc.y + sh.y, 0.0f);
    float o2 = fmaxf(v.z * sc.z + sh.z, 0.0f);
    float o3 = fmaxf(v.w * sc.w + sh.w, 0.0f);
    __nv_bfloat16 h0 = __float2bfloat16_rn(o0);
    __nv_bfloat16 h1 = __float2bfloat16_rn(o1);
    __nv_bfloat16 h2 = __float2bfloat16_rn(o2);
    __nv_bfloat16 h3 = __float2bfloat16_rn(o3);
    __nv_bfloat162* hp = reinterpret_cast<__nv_bfloat162*>(hi + (size_t)i * 4);
    __nv_bfloat162* lp = reinterpret_cast<__nv_bfloat162*>(lo + (size_t)i * 4);
    hp[0] = __nv_bfloat162(h0, h1);
    hp[1] = __nv_bfloat162(h2, h3);
    lp[0] = __nv_bfloat162(__float2bfloat16_rn(o0 - __bfloat162float(h0)),
                           __float2bfloat16_rn(o1 - __bfloat162float(h1)));
    lp[1] = __nv_bfloat162(__float2bfloat16_rn(o2 - __bfloat162float(h2)),
                           __float2bfloat16_rn(o3 - __bfloat162float(h3)));
}

// ---------------- launch ----------------
template <typename T>
static T* symp(const void* devSym) {
    void* p = nullptr;
    cudaGetSymbolAddress(&p, devSym);
    return reinterpret_cast<T*>(p);
}

extern "C" void kernel_launch(void* const* d_in, const int* in_sizes, int n_in,
                              void* d_out, int out_size) {
    const float* x   = (const float*)d_in[0];
    const int*   ei  = (const int*)  d_in[1];
    const float* W1  = (const float*)d_in[2];
    const float* b1  = (const float*)d_in[3];
    const float* gm1 = (const float*)d_in[4];
    const float* be1 = (const float*)d_in[5];
    const float* W2  = (const float*)d_in[6];
    const float* b2  = (const float*)d_in[7];
    const float* gm2 = (const float*)d_in[8];
    const float* be2 = (const float*)d_in[9];
    float* out = (float*)d_out;

    float* bufA   = symp<float>(g_bufA);
    float* bufB   = symp<float>(g_bufB);
    float* deg    = symp<float>(g_deg);
    float* dinv   = symp<float>(g_dinv);
    float* invdeg = symp<float>(g_invdeg);
    float* stats  = symp<float>(g_stats);
    float* scale  = symp<float>(g_scale);
    float* shift  = symp<float>(g_shift);
    __nv_bfloat16* xhi  = symp<__nv_bfloat16>(g_xhi);
    __nv_bfloat16* xlo  = symp<__nv_bfloat16>(g_xlo);
    __nv_bfloat16* h1hi = symp<__nv_bfloat16>(g_h1hi);
    __nv_bfloat16* h1lo = symp<__nv_bfloat16>(g_h1lo);
    __nv_bfloat16* w1hi = symp<__nv_bfloat16>(g_w1hi);
    __nv_bfloat16* w1lo = symp<__nv_bfloat16>(g_w1lo);
    __nv_bfloat16* w2hi = symp<__nv_bfloat16>(g_w2hi);
    __nv_bfloat16* w2lo = symp<__nv_bfloat16>(g_w2lo);

    // unconditional (no static guards); idempotent + capture-legal
    cudaFuncSetAttribute(k_mma_gemm,
                         cudaFuncAttributeMaxDynamicSharedMemorySize, GEMM_SMEM);

    const int T = 256;
    const int elem4 = NN * (HID / 4);
    const int ewGrid   = (elem4 + T - 1) / T;
    const int scGrid   = EE / 8;
    const int statGrid = (NN + BN_ROWS - 1) / BN_ROWS;
    const dim3 gemmGrid((NN + 127) / 128, 2);          // 782 x 2

    // ---- operand prep ----
    k_split<<<(NN * IN_DIM / 4 + T - 1) / T, T>>>(x, xhi, xlo, NN * IN_DIM / 4);
    k_splitWT<<<(IN_DIM * HID + T - 1) / T, T>>>(W1, w1hi, w1lo, IN_DIM);
    k_splitWT<<<(HID * HID + T - 1) / T, T>>>(W2, w2hi, w2lo, HID);

    // ---- degrees ----
    k_zero<<<(NN + T - 1) / T, T>>>(deg, NN);
    k_count_deg<<<(EE + T - 1) / T, T>>>(ei + EE, deg);
    k_finalize_deg<<<(NN + T - 1) / T, T>>>(deg, dinv, invdeg);

    // ---- layer 1 ----
    k_mma_gemm<<<gemmGrid, T, GEMM_SMEM>>>(xhi, xlo, w1hi, w1lo, bufA, NN, IN_DIM);
    k_agg_init<<<ewGrid, T>>>(bufB, bufA, invdeg, b1);
    k_scatter<<<scGrid, T>>>(bufB, bufA, ei, dinv);
    k_zero<<<2, T>>>(stats, 2 * HID);
    k_bn_stats<<<statGrid, T>>>(bufB, stats);
    k_bn_params<<<1, T>>>(stats, gm1, be1, scale, shift);
    k_bn_apply_split<<<ewGrid, T>>>(h1hi, h1lo, bufB, scale, shift);

    // ---- layer 2 ----
    k_mma_gemm<<<gemmGrid, T, GEMM_SMEM>>>(h1hi, h1lo, w2hi, w2lo, bufA, NN, HID);
    k_agg_init<<<ewGrid, T>>>(out, bufA, invdeg, b2);
    k_scatter<<<scGrid, T>>>(out, bufA, ei, dinv);
    k_zero<<<2, T>>>(stats, 2 * HID);
    k_bn_stats<<<statGrid, T>>>(out, stats);
    k_bn_params<<<1, T>>>(stats, gm2, be2, scale, shift);
    k_bn_apply<<<ewGrid, T>>>(out, out, scale, shift);
}